// round 1
// baseline (speedup 1.0000x reference)
#include <cuda_runtime.h>
#include <cuda_bf16.h>
#include <math.h>

// Problem constants
#define Bq 2
#define Tq 2048
#define Cq 1024
#define Hq 16
#define HDq 64
#define Mq (Bq*Tq)          // 4096 rows for all GEMMs

// Scratch (device globals — no allocation allowed)
__device__ float g_Q[Bq*Hq*Tq*HDq];   // [B,H,T,HD]
__device__ float g_K[Bq*Hq*Tq*HDq];
__device__ float g_V[Bq*Hq*Tq*HDq];
__device__ float g_O[Bq*Tq*Cq];       // merged heads [B,T,C]

// ---------------------------------------------------------------------------
// Tiled SGEMM:  out = A[4096,1024] * W[1024,1024] + bias
// BM=BN=64, BK=16, 256 threads, 4x4 register blocking.
// HEADOUT: write to [B,H,T,HD] layout (for Q/K/V projections); else row-major.
// ---------------------------------------------------------------------------
template<bool HEADOUT>
__global__ __launch_bounds__(256)
void proj_gemm(const float* __restrict__ A, const float* __restrict__ W,
               const float* __restrict__ bias, float* __restrict__ out)
{
    __shared__ float As[16][65];   // As[k][m], padded
    __shared__ float Bs[16][68];   // Bs[k][n], padded

    const int tid = threadIdx.x;
    const int tx  = tid & 15;          // 0..15 (N direction)
    const int ty  = tid >> 4;          // 0..15 (M direction)
    const int bm  = blockIdx.y * 64;
    const int bn  = blockIdx.x * 64;

    float acc[4][4] = {};

    for (int k0 = 0; k0 < Cq; k0 += 16) {
        // A tile 64x16 -> As[k][m] (transposed store). 256 float4 loads.
        {
            int r  = tid >> 2;         // 0..63
            int c4 = tid & 3;          // 0..3
            float4 va = *reinterpret_cast<const float4*>(
                A + (size_t)(bm + r) * Cq + k0 + c4 * 4);
            As[c4*4+0][r] = va.x;
            As[c4*4+1][r] = va.y;
            As[c4*4+2][r] = va.z;
            As[c4*4+3][r] = va.w;
        }
        // B tile 16x64 -> Bs[k][n]. 256 float4 loads (fully coalesced).
        {
            int r  = tid >> 4;         // 0..15
            int c4 = tid & 15;         // 0..15
            float4 vb = *reinterpret_cast<const float4*>(
                W + (size_t)(k0 + r) * Cq + bn + c4 * 4);
            *reinterpret_cast<float4*>(&Bs[r][c4*4]) = vb;
        }
        __syncthreads();

        #pragma unroll
        for (int k = 0; k < 16; k++) {
            float a[4], b[4];
            #pragma unroll
            for (int i = 0; i < 4; i++) a[i] = As[k][ty*4 + i];
            #pragma unroll
            for (int j = 0; j < 4; j++) b[j] = Bs[k][tx*4 + j];
            #pragma unroll
            for (int i = 0; i < 4; i++)
                #pragma unroll
                for (int j = 0; j < 4; j++)
                    acc[i][j] += a[i] * b[j];
        }
        __syncthreads();
    }

    // Epilogue: bias + store
    #pragma unroll
    for (int i = 0; i < 4; i++) {
        int m = bm + ty*4 + i;
        int b = m >> 11;               // m / T  (T=2048)
        int t = m & (Tq - 1);
        #pragma unroll
        for (int j = 0; j < 4; j++) {
            int n = bn + tx*4 + j;
            float v = acc[i][j] + bias[n];
            if (HEADOUT) {
                int h = n >> 6;        // n / 64
                int d = n & 63;
                out[(((size_t)(b*Hq + h) * Tq) + t) * HDq + d] = v;
            } else {
                out[(size_t)m * Cq + n] = v;
            }
        }
    }
}

// ---------------------------------------------------------------------------
// Flash attention, fp32. One block = 64 query rows of one (b,h).
// 64 threads; each thread owns one q row (q + o accumulator in registers).
// K/V tiles in smem (broadcast reads), S row in padded smem, online softmax.
// Output written merged-head into g_O [B,T,C].
// ---------------------------------------------------------------------------
__global__ __launch_bounds__(64)
void attn_kernel(const float* __restrict__ Q, const float* __restrict__ K,
                 const float* __restrict__ V, float* __restrict__ O)
{
    __shared__ float Ks[64*64];
    __shared__ float Vs[64*64];
    __shared__ float Ss[64*65];        // padded rows -> conflict-free

    const int tid = threadIdx.x;       // 0..63
    const int qt  = blockIdx.x * 64;
    const int h   = blockIdx.y;
    const int b   = blockIdx.z;

    const size_t headbase = ((size_t)(b*Hq + h) * Tq) * HDq;
    const float* Qb = Q + headbase;
    const float* Kb = K + headbase;
    const float* Vb = V + headbase;

    float q[64], o[64];
    {
        const float4* q4 = reinterpret_cast<const float4*>(Qb + (size_t)(qt + tid) * HDq);
        #pragma unroll
        for (int c = 0; c < 16; c++) {
            float4 v = q4[c];
            q[c*4+0] = v.x; q[c*4+1] = v.y; q[c*4+2] = v.z; q[c*4+3] = v.w;
        }
        #pragma unroll
        for (int c = 0; c < 64; c++) o[c] = 0.f;
    }

    float m = -INFINITY, l = 0.f;
    const float scale = 0.125f;        // 1/sqrt(64)

    for (int kt = 0; kt < Tq; kt += 64) {
        // Cooperative coalesced tile load: each tile is 4096 contiguous floats.
        {
            const float4* Kg4 = reinterpret_cast<const float4*>(Kb + (size_t)kt * HDq);
            const float4* Vg4 = reinterpret_cast<const float4*>(Vb + (size_t)kt * HDq);
            float4* Ks4 = reinterpret_cast<float4*>(Ks);
            float4* Vs4 = reinterpret_cast<float4*>(Vs);
            #pragma unroll
            for (int s = 0; s < 16; s++) {
                Ks4[tid + s*64] = Kg4[tid + s*64];
                Vs4[tid + s*64] = Vg4[tid + s*64];
            }
        }
        __syncthreads();

        // S = q . K^T  (scaled), tile max
        float tmax = -INFINITY;
        #pragma unroll 4
        for (int j = 0; j < 64; j++) {
            float s = 0.f;
            #pragma unroll
            for (int c = 0; c < 64; c++) s += q[c] * Ks[j*64 + c];
            s *= scale;
            Ss[tid*65 + j] = s;
            tmax = fmaxf(tmax, s);
        }

        float mnew  = fmaxf(m, tmax);
        float alpha = __expf(m - mnew);   // 0 on first tile (m=-inf)
        l *= alpha;
        #pragma unroll
        for (int c = 0; c < 64; c++) o[c] *= alpha;
        m = mnew;

        // P = exp(S - m); O += P * V
        #pragma unroll 2
        for (int j = 0; j < 64; j++) {
            float p = __expf(Ss[tid*65 + j] - mnew);
            l += p;
            #pragma unroll
            for (int c = 0; c < 64; c++) o[c] += p * Vs[j*64 + c];
        }
        __syncthreads();
    }

    const float inv = 1.f / l;
    float4* Ob = reinterpret_cast<float4*>(
        O + ((size_t)(b*Tq) + qt + tid) * Cq + h * HDq);
    #pragma unroll
    for (int c = 0; c < 16; c++) {
        float4 v;
        v.x = o[c*4+0]*inv; v.y = o[c*4+1]*inv;
        v.z = o[c*4+2]*inv; v.w = o[c*4+3]*inv;
        Ob[c] = v;
    }
}

// ---------------------------------------------------------------------------
// Launch
// ---------------------------------------------------------------------------
extern "C" void kernel_launch(void* const* d_in, const int* in_sizes, int n_in,
                              void* d_out, int out_size)
{
    (void)in_sizes; (void)n_in; (void)out_size;
    const float* queries = (const float*)d_in[0];
    const float* keys    = (const float*)d_in[1];
    const float* values  = (const float*)d_in[2];
    const float* Wq = (const float*)d_in[3];
    const float* bq = (const float*)d_in[4];
    const float* Wk = (const float*)d_in[5];
    const float* bk = (const float*)d_in[6];
    const float* Wv = (const float*)d_in[7];
    const float* bv = (const float*)d_in[8];
    const float* Wo = (const float*)d_in[9];
    const float* bo = (const float*)d_in[10];
    float* out = (float*)d_out;

    float *pQ, *pK, *pV, *pO;
    cudaGetSymbolAddress((void**)&pQ, g_Q);
    cudaGetSymbolAddress((void**)&pK, g_K);
    cudaGetSymbolAddress((void**)&pV, g_V);
    cudaGetSymbolAddress((void**)&pO, g_O);

    dim3 gg(Cq/64, Mq/64);             // (16, 64)
    proj_gemm<true><<<gg, 256>>>(queries, Wq, bq, pQ);
    proj_gemm<true><<<gg, 256>>>(keys,    Wk, bk, pK);
    proj_gemm<true><<<gg, 256>>>(values,  Wv, bv, pV);

    dim3 ga(Tq/64, Hq, Bq);            // (32, 16, 2)
    attn_kernel<<<ga, 64>>>(pQ, pK, pV, pO);

    proj_gemm<false><<<gg, 256>>>(pO, Wo, bo, out);
}